// round 7
// baseline (speedup 1.0000x reference)
#include <cuda_runtime.h>

// NEAT feed-forward DAG evaluator — R6: 2 CTAs/SM for cross-CTA latency hiding.
// x[4096,512] f32, W[1536,2048] f32 strictly lower-tri, b[1536], out[4096,256].
//
// Per CTA: BR=8 batch rows (256 threads, ~101.6KB smem -> 2 CTAs resident/SM).
// One CTA's serial triangle / barriers overlap the other CTA's GEMM.
// Per chunk of CC=64 nodes:
//   phase 1: panel GEMM, warp=k-split (8), per-thread 4r x 4c x 8k,
//            W staged as k-pair float2 (wS2[kpair][node]), double-buffered,
//            one barrier per 64-k block.
//   epilogue: split-K partials overlay the DEAD wS2 buffer; diagonal block
//            staged (j-pair layout) into the free wS2 buffer; reduce -> zACC.
//   phase 2: 64-node triangle, one warp per batch row.

#define NTHREADS 256
#define BR 8
#define CC 64
#define NIN 512
#define NEVAL 1536
#define NN 2048
#define NOUT 256
#define NCHUNK (NEVAL / CC)      // 24
#define SO 2052                  // outS row stride (floats); pad so row pairs
                                 // 4 apart land on different bank halves
#define WS2R 66                  // wS2 row stride in float2 units (16B-aligned rows)
#define WS2SZ (32 * WS2R)        // one buffer: 32 kpair rows (float2 units)
#define ZACCR 66

#define SMEM_FLOATS (BR*SO + 2*WS2SZ*2 + BR*ZACCR)
#define SMEM_BYTES (SMEM_FLOATS * 4)

__global__ void __launch_bounds__(NTHREADS, 2)
neat_ff_kernel(const float* __restrict__ x,
               const float* __restrict__ W,
               const float* __restrict__ bias,
               float* __restrict__ out)
{
    extern __shared__ float smem[];
    float*  outS = smem;                       // [BR][SO]
    float2* wS2  = (float2*)(outS + BR * SO);  // 2 x [32 kpair][WS2R]
    float*  zACC = (float*)(wS2 + 2 * WS2SZ);  // [BR][ZACCR] reduced z

    const int tid  = threadIdx.x;
    const int row0 = blockIdx.x * BR;

    // ---- load x tile (float4, coalesced) ----
    for (int i = tid; i < BR * (NIN / 4); i += NTHREADS) {
        int r = i >> 7, q = i & 127;
        *(float4*)&outS[r * SO + 4 * q] = *(const float4*)&x[(row0 + r) * NIN + 4 * q];
    }

    // GEMM mapping: warp = k-split sp (8k each); lane -> 4 rows x 4 cols
    const int sp   = tid >> 5;                 // 0..7 (uniform per warp)
    const int lane = tid & 31;
    const int cq   = lane & 15;  const int c0 = 4 * cq;
    const int rg   = lane >> 4;  const int r0 = 4 * rg;

    // staging: thread moves one node's 4 k-quads (node ssc, quads sq0+4p)
    const int ssc = tid >> 2;                  // 0..63
    const int sq0 = tid & 3;                   // quad base

    // prefetch first W block (chunk 0, kb 0)
    float4 v0 = *(const float4*)&W[ssc * NN + 4 * (sq0 + 0)];
    float4 v1 = *(const float4*)&W[ssc * NN + 4 * (sq0 + 4)];
    float4 v2 = *(const float4*)&W[ssc * NN + 4 * (sq0 + 8)];
    float4 v3 = *(const float4*)&W[ssc * NN + 4 * (sq0 + 12)];

    int buf = 0;

    for (int ch = 0; ch < NCHUNK; ch++) {
        const int i0 = ch * CC;
        const int g0 = NIN + i0;

        float acc[4][4];
        #pragma unroll
        for (int r = 0; r < 4; r++)
            #pragma unroll
            for (int c = 0; c < 4; c++) acc[r][c] = 0.0f;

        // ---- phase 1: panel GEMM, one barrier per 64-k block ----
        for (int kb = 0; kb < g0; kb += CC) {
            {   // commit prefetched block -> wS2[buf], k-pair layout
                float2* b = wS2 + buf * WS2SZ;
                b[(2*(sq0+ 0)  )*WS2R + ssc] = make_float2(v0.x, v0.y);
                b[(2*(sq0+ 0)+1)*WS2R + ssc] = make_float2(v0.z, v0.w);
                b[(2*(sq0+ 4)  )*WS2R + ssc] = make_float2(v1.x, v1.y);
                b[(2*(sq0+ 4)+1)*WS2R + ssc] = make_float2(v1.z, v1.w);
                b[(2*(sq0+ 8)  )*WS2R + ssc] = make_float2(v2.x, v2.y);
                b[(2*(sq0+ 8)+1)*WS2R + ssc] = make_float2(v2.z, v2.w);
                b[(2*(sq0+12)  )*WS2R + ssc] = make_float2(v3.x, v3.y);
                b[(2*(sq0+12)+1)*WS2R + ssc] = make_float2(v3.z, v3.w);
            }
            __syncthreads();
            {   // prefetch next block (diag block when nkb == g0)
                int nkb = kb + CC;
                const float* wr = &W[(i0 + ssc) * NN + nkb];
                v0 = *(const float4*)&wr[4 * (sq0 + 0)];
                v1 = *(const float4*)&wr[4 * (sq0 + 4)];
                v2 = *(const float4*)&wr[4 * (sq0 + 8)];
                v3 = *(const float4*)&wr[4 * (sq0 + 12)];
            }
            // micro-kernel: 2 quads of 4 k
            const float2* wb = wS2 + buf * WS2SZ;
            #pragma unroll
            for (int q = 0; q < 2; q++) {
                const int kk = 8 * sp + 4 * q;
                const int kp = 4 * sp + 2 * q;
                float4 w0 = *(const float4*)(wb +  kp      * WS2R + c0);
                float4 w1 = *(const float4*)(wb +  kp      * WS2R + c0 + 2);
                float4 w2 = *(const float4*)(wb + (kp + 1) * WS2R + c0);
                float4 w3 = *(const float4*)(wb + (kp + 1) * WS2R + c0 + 2);
                #pragma unroll
                for (int r = 0; r < 4; r++) {
                    float4 a = *(const float4*)&outS[(r0 + r) * SO + kb + kk];
                    acc[r][0] = fmaf(a.x, w0.x, acc[r][0]);
                    acc[r][1] = fmaf(a.x, w0.z, acc[r][1]);
                    acc[r][2] = fmaf(a.x, w1.x, acc[r][2]);
                    acc[r][3] = fmaf(a.x, w1.z, acc[r][3]);
                    acc[r][0] = fmaf(a.y, w0.y, acc[r][0]);
                    acc[r][1] = fmaf(a.y, w0.w, acc[r][1]);
                    acc[r][2] = fmaf(a.y, w1.y, acc[r][2]);
                    acc[r][3] = fmaf(a.y, w1.w, acc[r][3]);
                    acc[r][0] = fmaf(a.z, w2.x, acc[r][0]);
                    acc[r][1] = fmaf(a.z, w2.z, acc[r][1]);
                    acc[r][2] = fmaf(a.z, w3.x, acc[r][2]);
                    acc[r][3] = fmaf(a.z, w3.z, acc[r][3]);
                    acc[r][0] = fmaf(a.w, w2.y, acc[r][0]);
                    acc[r][1] = fmaf(a.w, w2.w, acc[r][1]);
                    acc[r][2] = fmaf(a.w, w3.y, acc[r][2]);
                    acc[r][3] = fmaf(a.w, w3.w, acc[r][3]);
                }
            }
            buf ^= 1;
        }
        // after loop: buf == free buffer (last block used buf^1)
        const int bufFree = buf, bufLast = buf ^ 1;

        __syncthreads();   // all compute of last block done before overlays

        // split-K partials -> overlay region of the DEAD buffer (bufLast)
        float* zSb = (float*)(wS2 + bufLast * WS2SZ);
        #pragma unroll
        for (int r = 0; r < 4; r++)
            *(float4*)&zSb[(sp * BR + r0 + r) * 64 + c0] =
                make_float4(acc[r][0], acc[r][1], acc[r][2], acc[r][3]);
        {   // diag block (in v) -> wS2[bufFree], j-pair layout
            float2* b = wS2 + bufFree * WS2SZ;
            b[(2*(sq0+ 0)  )*WS2R + ssc] = make_float2(v0.x, v0.y);
            b[(2*(sq0+ 0)+1)*WS2R + ssc] = make_float2(v0.z, v0.w);
            b[(2*(sq0+ 4)  )*WS2R + ssc] = make_float2(v1.x, v1.y);
            b[(2*(sq0+ 4)+1)*WS2R + ssc] = make_float2(v1.z, v1.w);
            b[(2*(sq0+ 8)  )*WS2R + ssc] = make_float2(v2.x, v2.y);
            b[(2*(sq0+ 8)+1)*WS2R + ssc] = make_float2(v2.z, v2.w);
            b[(2*(sq0+12)  )*WS2R + ssc] = make_float2(v3.x, v3.y);
            b[(2*(sq0+12)+1)*WS2R + ssc] = make_float2(v3.z, v3.w);
        }
        // prefetch first block of next chunk (overlaps reduce + triangle)
        if (ch + 1 < NCHUNK) {
            const float* wr = &W[(i0 + CC + ssc) * NN];
            v0 = *(const float4*)&wr[4 * (sq0 + 0)];
            v1 = *(const float4*)&wr[4 * (sq0 + 4)];
            v2 = *(const float4*)&wr[4 * (sq0 + 8)];
            v3 = *(const float4*)&wr[4 * (sq0 + 12)];
        }
        __syncthreads();   // zSb + diag visible

        // reduce 8 split-K partials -> zACC
        #pragma unroll
        for (int t = 0; t < 2; t++) {
            int idx = tid + t * NTHREADS;
            int k = idx & 63, r = idx >> 6;
            float s = zSb[r * 64 + k];
            #pragma unroll
            for (int s8 = 1; s8 < 8; s8++)
                s += zSb[(s8 * BR + r) * 64 + k];
            zACC[r * ZACCR + k] = s;
        }
        __syncthreads();   // zACC visible; bufLast free for next chunk commits

        // ---- phase 2: triangle, one warp per batch row (8 warps busy) ----
        {
            const int r  = sp;                 // warp -> batch row
            const int k0 = lane, k1 = lane + 32;
            float a0t = __ldg(&bias[i0 + k0]) + zACC[r * ZACCR + k0];
            float a1t = __ldg(&bias[i0 + k1]) + zACC[r * ZACCR + k1];
            float o0 = 0.f, o1 = 0.f;
            const float2* wd = wS2 + bufFree * WS2SZ;
            #pragma unroll 4
            for (int jp = 0; jp < 32; jp++) {
                float2 wp0 = wd[jp * WS2R + k0];   // W[k0][2jp], W[k0][2jp+1]
                float2 wp1 = wd[jp * WS2R + k1];
                #pragma unroll
                for (int h = 0; h < 2; h++) {
                    int j = 2 * jp + h;
                    float w0 = h ? wp0.y : wp0.x;
                    float w1 = h ? wp1.y : wp1.x;
                    float zj = __shfl_sync(0xffffffffu, (j < 32) ? a0t : a1t, j & 31);
                    float t5 = fminf(fmaxf(5.0f * zj, -60.0f), 60.0f);
                    float o  = __fdividef(1.0f, 1.0f + __expf(-t5));
                    if (j == k0) o0 = o;
                    if (j == k1) o1 = o;
                    if (k0 > j) a0t = fmaf(w0, o, a0t);
                    if (k1 > j) a1t = fmaf(w1, o, a1t);
                }
            }
            outS[r * SO + g0 + k0] = o0;
            outS[r * SO + g0 + k1] = o1;
        }
        // next commit targets bufLast; block-iter barrier orders it vs triangle
        buf = bufLast;
    }

    __syncthreads();
    // ---- write output: last NOUT columns ----
    for (int i = tid; i < BR * (NOUT / 4); i += NTHREADS) {
        int r = i >> 6, q = i & 63;
        *(float4*)&out[(row0 + r) * NOUT + 4 * q] =
            *(const float4*)&outS[r * SO + (NN - NOUT) + 4 * q];
    }
}

extern "C" void kernel_launch(void* const* d_in, const int* in_sizes, int n_in,
                              void* d_out, int out_size) {
    const float* x    = (const float*)d_in[0];
    const float* W    = (const float*)d_in[1];
    const float* bias = (const float*)d_in[2];
    float* out        = (float*)d_out;
    (void)in_sizes; (void)n_in; (void)out_size;

    cudaFuncSetAttribute(neat_ff_kernel,
                         cudaFuncAttributeMaxDynamicSharedMemorySize,
                         SMEM_BYTES);
    neat_ff_kernel<<<4096 / BR, NTHREADS, SMEM_BYTES>>>(x, W, bias, out);
}

// round 11
// speedup vs baseline: 3.2575x; 3.2575x over previous
#include <cuda_runtime.h>
#include <cuda_bf16.h>
#include <cstdint>

// NEAT DAG — R10: warp-level mma.sync bf16 hi/lo 3-pass. R9 + triangle
// indexing fix: use W[node k][col j] (lower-tri), not the transposed (zero)
// element.
// x[4096,512] f32, W[1536,2048] f32 lower-tri, b[1536], out[4096,256].

#define NTH 256
#define BR 32
#define NIN 512
#define NN 2048
#define NCHUNK 24
#define ZST 66

__device__ __align__(256) __nv_bfloat16 g_Ahi[4096u * 2048u];
__device__ __align__(256) __nv_bfloat16 g_Alo[4096u * 2048u];
__device__ __align__(256) __nv_bfloat16 g_Whi[1536u * 2048u];
__device__ __align__(256) __nv_bfloat16 g_Wlo[1536u * 2048u];

// ---- smem layout (bytes) ----
#define OFF_BIAS 0
#define OFF_OS   256
#define OFF_ZSM  1536
#define OFF_WD   9984
#define OFF_BUF0 28672
#define BUFSZ    24576
#define OFF_BUF1 (OFF_BUF0 + BUFSZ)
#define SMEM_SZ  (OFF_BUF1 + BUFSZ)   // 77824
#define AHI 0
#define ALO 4096
#define WHI 8192
#define WLO 16384

#define SW128(b) ((b) ^ (((b) >> 3) & 0x70))

__device__ __forceinline__ uint32_t smem_u32(const void* p) {
    uint32_t a;
    asm("{ .reg .u64 t; cvta.to.shared.u64 t, %1; cvt.u32.u64 %0, t; }" : "=r"(a) : "l"(p));
    return a;
}
__device__ __forceinline__ void ldm4(uint32_t* r, uint32_t addr) {
    asm volatile("ldmatrix.sync.aligned.m8n8.x4.shared.b16 {%0,%1,%2,%3}, [%4];"
                 : "=r"(r[0]), "=r"(r[1]), "=r"(r[2]), "=r"(r[3]) : "r"(addr));
}
__device__ __forceinline__ void mma_bf16(float* d, const uint32_t* a,
                                         uint32_t b0, uint32_t b1) {
    asm volatile(
        "mma.sync.aligned.m16n8k16.row.col.f32.bf16.bf16.f32 "
        "{%0,%1,%2,%3}, {%4,%5,%6,%7}, {%8,%9}, {%0,%1,%2,%3};"
        : "+f"(d[0]), "+f"(d[1]), "+f"(d[2]), "+f"(d[3])
        : "r"(a[0]), "r"(a[1]), "r"(a[2]), "r"(a[3]), "r"(b0), "r"(b1));
}
__device__ __forceinline__ void split4(float4 v, __nv_bfloat16* h, __nv_bfloat16* l) {
    float f[4] = {v.x, v.y, v.z, v.w};
    #pragma unroll
    for (int j = 0; j < 4; j++) {
        h[j] = __float2bfloat16(f[j]);
        l[j] = __float2bfloat16(f[j] - __bfloat162float(h[j]));
    }
}

#define XN4 (4096 * 512 / 4)
#define WN4 (1536 * 2048 / 4)
__global__ void conv_kernel(const float* __restrict__ x, const float* __restrict__ W) {
    int idx = blockIdx.x * blockDim.x + threadIdx.x;
    __align__(8) __nv_bfloat16 h[4], l[4];
    if (idx < XN4) {
        int r = idx >> 7, c = (idx & 127) * 4;
        split4(*(const float4*)&x[(size_t)r * NIN + c], h, l);
        size_t o = (size_t)r * NN + c;
        *(uint2*)&g_Ahi[o] = *(uint2*)h;
        *(uint2*)&g_Alo[o] = *(uint2*)l;
    } else if (idx < XN4 + WN4) {
        int j = idx - XN4;
        int r = j >> 9, c = (j & 511) * 4;
        size_t o = (size_t)r * NN + c;
        split4(*(const float4*)&W[o], h, l);
        *(uint2*)&g_Whi[o] = *(uint2*)h;
        *(uint2*)&g_Wlo[o] = *(uint2*)l;
    }
}

__global__ void __launch_bounds__(NTH, 2)
neat_mma_kernel(const float* __restrict__ W,
                const float* __restrict__ bias,
                float* __restrict__ out)
{
    extern __shared__ char sm[];
    const uint32_t sb = smem_u32(sm);
    const int tid = threadIdx.x;
    const int lane = tid & 31, wrp = tid >> 5;
    const int row0 = blockIdx.x * BR;

    float* biasS = (float*)(sm + OFF_BIAS);
    float* oS    = (float*)(sm + OFF_OS);     // [32][9]
    float* zSm   = (float*)(sm + OFF_ZSM);    // [32][66]
    float* Wd    = (float*)(sm + OFF_WD);     // [64][68] fp32 diag, Wd[r][q]=W[i0+r][g0+q]

    const int rt16 = (wrp & 1) * 16;
    const int c0   = (wrp >> 1) * 16;
    const int mrow = lane & 7, mid = lane >> 3;
    const int aRowB = (rt16 + mrow + ((mid & 1) << 3)) * 128 + ((mid >> 1) << 4);
    const int wRowB = (c0 + mrow + ((mid >> 1) << 3)) * 128 + ((mid & 1) << 4);

    const int sr = tid >> 3, sg = tid & 7;
    const uint32_t soA  = SW128((uint32_t)(sr * 128 + sg * 16));
    const uint32_t soW1 = SW128((uint32_t)((sr + 32) * 128 + sg * 16));

    uint4 pAh, pAl, pW0h, pW0l, pW1h, pW1l;
    {
        size_t ga = (size_t)(row0 + sr) * NN + 8 * sg;
        pAh = *(const uint4*)&g_Ahi[ga];
        pAl = *(const uint4*)&g_Alo[ga];
        size_t g0w = (size_t)sr * NN + 8 * sg;
        size_t g1w = (size_t)(sr + 32) * NN + 8 * sg;
        pW0h = *(const uint4*)&g_Whi[g0w];
        pW0l = *(const uint4*)&g_Wlo[g0w];
        pW1h = *(const uint4*)&g_Whi[g1w];
        pW1l = *(const uint4*)&g_Wlo[g1w];
    }
    int blk = 0;

    for (int ch = 0; ch < NCHUNK; ch++) {
        const int i0 = ch * 64, g0 = NIN + i0;
        float d0[4] = {0.f, 0.f, 0.f, 0.f}, d1[4] = {0.f, 0.f, 0.f, 0.f};

        // ---- panel GEMM over K blocks [0, g0) ----
        for (int kb = 0; kb < g0; kb += 64) {
            char* bp = sm + ((blk & 1) ? OFF_BUF1 : OFF_BUF0);
            *(uint4*)(bp + AHI + soA)  = pAh;
            *(uint4*)(bp + ALO + soA)  = pAl;
            *(uint4*)(bp + WHI + soA)  = pW0h;
            *(uint4*)(bp + WLO + soA)  = pW0l;
            *(uint4*)(bp + WHI + soW1) = pW1h;
            *(uint4*)(bp + WLO + soW1) = pW1l;
            __syncthreads();
            {
                int nkb = kb + 64, nch = ch;
                if (nkb >= g0) { nch = ch + 1; nkb = 0; }
                if (nch < NCHUNK) {
                    int ni0 = nch * 64;
                    size_t ga = (size_t)(row0 + sr) * NN + nkb + 8 * sg;
                    pAh = *(const uint4*)&g_Ahi[ga];
                    pAl = *(const uint4*)&g_Alo[ga];
                    size_t g0w = (size_t)(ni0 + sr) * NN + nkb + 8 * sg;
                    size_t g1w = (size_t)(ni0 + sr + 32) * NN + nkb + 8 * sg;
                    pW0h = *(const uint4*)&g_Whi[g0w];
                    pW0l = *(const uint4*)&g_Wlo[g0w];
                    pW1h = *(const uint4*)&g_Whi[g1w];
                    pW1l = *(const uint4*)&g_Wlo[g1w];
                }
            }
            const uint32_t bb = sb + ((blk & 1) ? OFF_BUF1 : OFF_BUF0);
            #pragma unroll
            for (int ks = 0; ks < 4; ks++) {
                uint32_t ao = (uint32_t)(aRowB + 32 * ks);
                uint32_t wo = (uint32_t)(wRowB + 32 * ks);
                uint32_t ah[4], al[4], wh[4], wl[4];
                ldm4(ah, bb + AHI + SW128(ao));
                ldm4(al, bb + ALO + SW128(ao));
                ldm4(wh, bb + WHI + SW128(wo));
                ldm4(wl, bb + WLO + SW128(wo));
                mma_bf16(d0, ah, wh[0], wh[1]);
                mma_bf16(d0, ah, wl[0], wl[1]);
                mma_bf16(d0, al, wh[0], wh[1]);
                mma_bf16(d1, ah, wh[2], wh[3]);
                mma_bf16(d1, ah, wl[2], wl[3]);
                mma_bf16(d1, al, wh[2], wh[3]);
            }
            blk++;
        }

        // ---- stage fp32 diagonal block + bias ----
        #pragma unroll
        for (int i = 0; i < 4; i++) {
            int idx = tid + i * NTH;
            int r = idx >> 4, q = idx & 15;
            *(float4*)&Wd[r * 68 + 4 * q] =
                *(const float4*)&W[(size_t)(i0 + r) * NN + g0 + 4 * q];
        }
        if (tid < 64) biasS[tid] = bias[i0 + tid];
        __syncthreads();

        // ---- write z fragments (+bias) to zSm ----
        {
            int rw = rt16 + (lane >> 2);
            int cb = c0 + 2 * (lane & 3);
            *(float2*)&zSm[rw * ZST + cb] =
                make_float2(d0[0] + biasS[cb], d0[1] + biasS[cb + 1]);
            *(float2*)&zSm[(rw + 8) * ZST + cb] =
                make_float2(d0[2] + biasS[cb], d0[3] + biasS[cb + 1]);
            *(float2*)&zSm[rw * ZST + cb + 8] =
                make_float2(d1[0] + biasS[cb + 8], d1[1] + biasS[cb + 9]);
            *(float2*)&zSm[(rw + 8) * ZST + cb + 8] =
                make_float2(d1[2] + biasS[cb + 8], d1[3] + biasS[cb + 9]);
        }
        __syncthreads();

        // ---- triangle: 8 sub-blocks of 8 nodes ----
        for (int s = 0; s < 8; s++) {
            if (tid < 32) {
                int row = tid;
                float zl[8], ov[8];
                #pragma unroll
                for (int j = 0; j < 8; j++) zl[j] = zSm[row * ZST + 8 * s + j];
                #pragma unroll
                for (int j = 0; j < 8; j++) {
                    float t5 = fminf(fmaxf(5.0f * zl[j], -60.0f), 60.0f);
                    float o  = __fdividef(1.0f, 1.0f + __expf(-t5));
                    ov[j] = o;
                    // z_k += W[node 8s+k][col g0+8s+j] * o_j   (k > j)
                    #pragma unroll
                    for (int k = j + 1; k < 8; k++)
                        zl[k] = fmaf(Wd[(8 * s + k) * 68 + (8 * s + j)], o, zl[k]);
                }
                #pragma unroll
                for (int j = 0; j < 8; j++) oS[row * 9 + j] = ov[j];
                __align__(16) __nv_bfloat16 hh[8], ll[8];
                #pragma unroll
                for (int j = 0; j < 8; j++) {
                    hh[j] = __float2bfloat16(ov[j]);
                    ll[j] = __float2bfloat16(ov[j] - __bfloat162float(hh[j]));
                }
                size_t go = (size_t)(row0 + row) * NN + g0 + 8 * s;
                *(uint4*)&g_Ahi[go] = *(uint4*)hh;
                *(uint4*)&g_Alo[go] = *(uint4*)ll;
                int col0 = g0 + 8 * s;
                if (col0 >= NN - 256) {
                    int oc = col0 - (NN - 256);
                    #pragma unroll
                    for (int j = 0; j < 8; j++)
                        out[(size_t)(row0 + row) * 256 + oc + j] = ov[j];
                }
            }
            __syncthreads();
            if (s < 7) {
                int row = lane;
                float ov[8];
                #pragma unroll
                for (int j = 0; j < 8; j++) ov[j] = oS[row * 9 + j];
                for (int k = 8 * (s + 1) + wrp; k < 64; k += 8) {
                    float z = zSm[row * ZST + k];
                    // z_k += W[node k][col g0+8s+j] * o_j
                    #pragma unroll
                    for (int j = 0; j < 8; j++)
                        z = fmaf(ov[j], Wd[k * 68 + (8 * s + j)], z);
                    zSm[row * ZST + k] = z;
                }
                __syncthreads();
            }
        }
        __syncthreads();
    }
}

extern "C" void kernel_launch(void* const* d_in, const int* in_sizes, int n_in,
                              void* d_out, int out_size) {
    const float* x    = (const float*)d_in[0];
    const float* W    = (const float*)d_in[1];
    const float* bias = (const float*)d_in[2];
    float* out        = (float*)d_out;
    (void)in_sizes; (void)n_in; (void)out_size;

    conv_kernel<<<(XN4 + WN4 + NTH - 1) / NTH, NTH>>>(x, W);
    cudaFuncSetAttribute(neat_mma_kernel,
                         cudaFuncAttributeMaxDynamicSharedMemorySize, SMEM_SZ);
    neat_mma_kernel<<<4096 / BR, NTH, SMEM_SZ>>>(W, bias, out);
}